// round 2
// baseline (speedup 1.0000x reference)
#include <cuda_runtime.h>
#include <math.h>

#define NCLS 1000
#define NV4  250   // 1000 floats = 250 float4 per row

__device__ __forceinline__ void atomicMaxFloat(float* addr, float val) {
    int* ia = (int*)addr;
    int old = *ia;
    while (val > __int_as_float(old)) {
        int assumed = old;
        old = atomicCAS(ia, assumed, __float_as_int(val));
        if (old == assumed) break;
    }
}

__global__ void init_kernel(float* out_max) {
    if (threadIdx.x == 0) *out_max = -INFINITY;
}

__global__ __launch_bounds__(256, 4) void margin_kernel(
    const float* __restrict__ o1, const float* __restrict__ o2,
    const float* __restrict__ o3, const float* __restrict__ o4,
    const float* __restrict__ mim, const int* __restrict__ targets,
    float* __restrict__ out_max, float* __restrict__ out_thr)
{
    const int row = blockIdx.x;
    const int tid = threadIdx.x;
    const int t   = targets[row];    // int32 (JAX x64 disabled -> int64 decays to int32)

    const float* mats[5] = {o1, o2, o3, o4, mim};

    __shared__ float  s_tgt[5];
    __shared__ float2 s_red[5][8];
    __shared__ float  s_gmax[8];

    if (tid < 5) s_tgt[tid] = -INFINITY;   // defensive init (no stale smem)

    // ---- load phase: 5 independent float4 loads per thread (MLP=5) ----
    float4 v[5];
    if (tid < NV4) {
        const size_t base = (size_t)row * NCLS;
        #pragma unroll
        for (int m = 0; m < 5; m++)
            v[m] = reinterpret_cast<const float4*>(mats[m] + base)[tid];
    }

    // ---- per-thread top2 + target pick + global max (mats 0..3) ----
    float m1[5], m2[5];
    float gmax = -INFINITY;
    #pragma unroll
    for (int m = 0; m < 5; m++) {
        float a = -INFINITY, b = -INFINITY, c = -INFINITY, d = -INFINITY;
        if (tid < NV4) { a = v[m].x; b = v[m].y; c = v[m].z; d = v[m].w; }
        float hi1 = fmaxf(a, b), lo1 = fminf(a, b);
        float hi2 = fmaxf(c, d), lo2 = fminf(c, d);
        float M1 = fmaxf(hi1, hi2);
        float M2 = fmaxf(fminf(hi1, hi2), fmaxf(lo1, lo2));
        m1[m] = M1; m2[m] = M2;
        if (m < 4) gmax = fmaxf(gmax, M1);
        if (tid == (t >> 2)) {
            float vals[4] = {a, b, c, d};
            s_tgt[m] = vals[t & 3];
        }
    }

    // ---- warp-level top2 reduction ----
    const unsigned full = 0xFFFFFFFFu;
    #pragma unroll
    for (int off = 16; off; off >>= 1) {
        #pragma unroll
        for (int m = 0; m < 5; m++) {
            float p1 = __shfl_down_sync(full, m1[m], off);
            float p2 = __shfl_down_sync(full, m2[m], off);
            float n1 = fmaxf(m1[m], p1);
            float n2 = fmaxf(fminf(m1[m], p1), fmaxf(m2[m], p2));
            m1[m] = n1; m2[m] = n2;
        }
        gmax = fmaxf(gmax, __shfl_down_sync(full, gmax, off));
    }

    const int warp = tid >> 5, lane = tid & 31;
    if (lane == 0) {
        #pragma unroll
        for (int m = 0; m < 5; m++) s_red[m][warp] = make_float2(m1[m], m2[m]);
        s_gmax[warp] = gmax;
    }
    __syncthreads();

    // ---- final combine + softmax by thread 0 ----
    if (tid == 0) {
        float g = s_gmax[0];
        #pragma unroll
        for (int w = 1; w < 8; w++) g = fmaxf(g, s_gmax[w]);
        atomicMaxFloat(out_max, g);

        float margin[5];
        #pragma unroll
        for (int m = 0; m < 5; m++) {
            float M1 = -INFINITY, M2 = -INFINITY;
            #pragma unroll
            for (int w = 0; w < 8; w++) {
                float2 p = s_red[m][w];
                float n1 = fmaxf(M1, p.x);
                M2 = fmaxf(fminf(M1, p.x), fmaxf(M2, p.y));
                M1 = n1;
            }
            float tv = s_tgt[m];
            // margin/TEMPERATURE folded in (TEMPERATURE = 2.0)
            margin[m] = (M1 == tv) ? (M1 - M2) * 0.5f : 0.0f;
        }

        float mx = margin[0];
        #pragma unroll
        for (int m = 1; m < 5; m++) mx = fmaxf(mx, margin[m]);
        float e[5], s = 0.0f;
        #pragma unroll
        for (int m = 0; m < 5; m++) { e[m] = __expf(margin[m] - mx); s += e[m]; }
        float inv = 1.0f / s;
        float* dst = out_thr + (size_t)row * 5;
        #pragma unroll
        for (int m = 0; m < 5; m++) dst[m] = e[m] * inv;
    }
}

extern "C" void kernel_launch(void* const* d_in, const int* in_sizes, int n_in,
                              void* d_out, int out_size)
{
    const float* o1  = (const float*)d_in[0];
    const float* o2  = (const float*)d_in[1];
    const float* o3  = (const float*)d_in[2];
    const float* o4  = (const float*)d_in[3];
    const float* mim = (const float*)d_in[4];
    const int*   tgt = (const int*)d_in[5];

    const int n = in_sizes[5];          // 16384 rows (targets element count)
    float* out = (float*)d_out;

    // Tuple flattened in return order: [max_preds (scalar), out_threshold (n*5)].
    float* out_thr = out + ((size_t)out_size - (size_t)n * 5);
    float* out_max = out;

    init_kernel<<<1, 32>>>(out_max);
    margin_kernel<<<n, 256>>>(o1, o2, o3, o4, mim, tgt, out_max, out_thr);
}